// round 15
// baseline (speedup 1.0000x reference)
#include <cuda_runtime.h>
#include <cuda_fp16.h>
#include <math.h>
#include <stdint.h>

#define N_NODES 100000
#define N_EDGES 600000
#define N_GRAPHS 1024
#define F_IN 32
#define GHC 128
#define NHID 512
#define NOUT 256
#define N_LAYERS 5
#define BN_EPS 1e-5f
#define ZDIM (N_LAYERS * GHC)   // 640

// packed fp16 weight offsets (elements)
#define OFF_W1_0 0
#define OFF_W2_0 8192
#define OFF_W1S  40960
#define OFF_W2S  172032
#define OFF_WM1  303104
#define OFF_WM2  630784
#define W_TOTAL  761856

// ---------------- device scratch ----------------
__device__ __half g_hsum[N_NODES * GHC];
__device__ __half g_hid [N_NODES * 2 * GHC];
__device__ __half g_pre [N_NODES * GHC];
__device__ __half g_h   [N_NODES * GHC];
__device__ __half g_wtf [W_TOTAL];           // PACKED fp16 weights (frag order)
__device__ int    g_rowptr[N_NODES + 1];
__device__ int    g_deg   [N_NODES];
__device__ int    g_csr   [N_EDGES];
__device__ int    g_blocktotals[128];
__device__ volatile int g_scanflag[128];
__device__ float  g_fsum[2][GHC], g_fsq[2][GHC];   // double-buffered by layer parity
__device__ __half g_z  [N_GRAPHS * ZDIM];
__device__ __half g_zh [N_GRAPHS * NHID];
__device__ int    g_gstart[N_GRAPHS + 1];
__device__ int    g_is64;

// ---------------- helpers ----------------
__device__ __forceinline__ int ld_idx(const void* p, long i) {
    if (g_is64) return (int)((const long long*)p)[i];
    return ((const int*)p)[i];
}
__device__ __forceinline__ void cp16(uint32_t saddr, const void* g, unsigned sz) {
    asm volatile("cp.async.cg.shared.global [%0], [%1], 16, %2;"
                 :: "r"(saddr), "l"(g), "r"(sz));
}
__device__ __forceinline__ void cpcommit() { asm volatile("cp.async.commit_group;"); }
template<int W> __device__ __forceinline__ void cpwait() {
    asm volatile("cp.async.wait_group %0;" :: "n"(W));
}
__device__ __forceinline__ void mma_f16(float* c, uint32_t a0, uint32_t a1,
                                        uint32_t a2, uint32_t a3,
                                        uint32_t b0, uint32_t b1) {
    asm volatile(
        "mma.sync.aligned.m16n8k16.row.col.f32.f16.f16.f32 "
        "{%0,%1,%2,%3},{%4,%5,%6,%7},{%8,%9},{%0,%1,%2,%3};"
        : "+f"(c[0]), "+f"(c[1]), "+f"(c[2]), "+f"(c[3])
        : "r"(a0), "r"(a1), "r"(a2), "r"(a3), "r"(b0), "r"(b1));
}
__device__ __forceinline__ void bn_coef(int par, int c,
                                        const float* gamma, const float* beta,
                                        float& sc, float& sh) {
    double mu = (double)g_fsum[par][c] / (double)N_NODES;
    double var = (double)g_fsq[par][c] / (double)N_NODES - mu * mu;
    double inv = 1.0 / sqrt(var + (double)BN_EPS);
    double s = (double)gamma[c] * inv;
    sc = (float)s;
    sh = (float)((double)beta[c] - mu * s);
}

__global__ void k_probe(const unsigned int* ei_words) {
    if (threadIdx.x == 0 && blockIdx.x == 0) {
        unsigned int nz = 0;
        for (int i = 0; i < 256; i++) nz |= ei_words[2 * i + 1];
        g_is64 = (nz == 0) ? 1 : 0;
    }
}

__global__ void k_init_graph(const void* batch) {
    int i = blockIdx.x * blockDim.x + threadIdx.x;
    if (i < N_NODES) g_deg[i] = 0;
    if (i < 128) { g_scanflag[i] = 0; g_blocktotals[i] = 0; }
    if (i <= N_GRAPHS) {
        int g = i, lo = 0, hi = N_NODES;
        while (lo < hi) {
            int mid = (lo + hi) >> 1;
            if (ld_idx(batch, mid) < g) lo = mid + 1; else hi = mid;
        }
        g_gstart[i] = lo;
    }
}

// pack one uint4 slot (8 halves) of a weight matrix into m16n8k16 B-frag order
__device__ __forceinline__ void pack_slot(const float* W, int K, int N,
                                          long rel4, __half* dst) {
    int lane = (int)(rel4 & 31);
    int q    = (int)((rel4 >> 5) & 3);
    int wn2  = (int)((rel4 >> 7) & 1);
    int kk16 = (int)((rel4 >> 8) & 1);
    long slab = rel4 >> 9;
    int ktiles = K >> 5;
    int nb = (int)(slab / ktiles);
    int kt = (int)(slab % ktiles);
    int gr = lane >> 2, tg = lane & 3;
    int kb = kt * 32 + kk16 * 16 + 2 * tg;
    int c0 = nb * 128 + wn2 * 64 + q * 16 + gr;
    int c1 = c0 + 8;
    __half h[8];
    h[0] = __float2half_rn(W[(long)kb * N + c0]);
    h[1] = __float2half_rn(W[(long)(kb + 1) * N + c0]);
    h[2] = __float2half_rn(W[(long)(kb + 8) * N + c0]);
    h[3] = __float2half_rn(W[(long)(kb + 9) * N + c0]);
    h[4] = __float2half_rn(W[(long)kb * N + c1]);
    h[5] = __float2half_rn(W[(long)(kb + 1) * N + c1]);
    h[6] = __float2half_rn(W[(long)(kb + 8) * N + c1]);
    h[7] = __float2half_rn(W[(long)(kb + 9) * N + c1]);
    *(uint4*)dst = *(uint4*)h;
}

__global__ void k_init_wpack(const float* W1_0, const float* W2_0,
                             const float* W1s, const float* W2s,
                             const float* Wm1, const float* Wm2) {
    int i = blockIdx.x * blockDim.x + threadIdx.x;   // uint4 slot
    if (i >= W_TOTAL / 8) return;
    long f = (long)i * 8;
    __half* dst = &g_wtf[f];
    if (f < OFF_W2_0) {
        pack_slot(W1_0, 32, 256, f / 8, dst);
    } else if (f < OFF_W1S) {
        pack_slot(W2_0, 256, 128, (f - OFF_W2_0) / 8, dst);
    } else if (f < OFF_W2S) {
        long rel = f - OFF_W1S;
        int l = (int)(rel / 32768);
        pack_slot(W1s + (long)l * 32768, 128, 256, (rel % 32768) / 8, dst);
    } else if (f < OFF_WM1) {
        long rel = f - OFF_W2S;
        int l = (int)(rel / 32768);
        pack_slot(W2s + (long)l * 32768, 256, 128, (rel % 32768) / 8, dst);
    } else if (f < OFF_WM2) {
        pack_slot(Wm1, 640, 512, (f - OFF_WM1) / 8, dst);
    } else {
        pack_slot(Wm2, 512, 256, (f - OFF_WM2) / 8, dst);
    }
}

__global__ void k_deg(const void* ei) {
    int e = blockIdx.x * blockDim.x + threadIdx.x;
    if (e < N_EDGES) {
        int dst = ld_idx(ei, (long)N_EDGES + e);
        atomicAdd(&g_deg[dst], 1);
    }
}

__global__ void k_scan() {
    __shared__ int sh[1024];
    __shared__ int s_off;
    int b = blockIdx.x, t = threadIdx.x;
    int gid = b * 1024 + t;
    int v = (gid < N_NODES) ? g_deg[gid] : 0;
    sh[t] = v;
    __syncthreads();
    for (int off = 1; off < 1024; off <<= 1) {
        int tmp = (t >= off) ? sh[t - off] : 0;
        __syncthreads();
        sh[t] += tmp;
        __syncthreads();
    }
    if (t == 1023) {
        g_blocktotals[b] = sh[1023];
        __threadfence();
        g_scanflag[b] = 1;
    }
    if (t == 0) s_off = 0;
    __syncthreads();
    if (t < b) {
        while (g_scanflag[t] == 0) {}
        int tot = atomicAdd(&g_blocktotals[t], 0);
        atomicAdd(&s_off, tot);
    }
    __syncthreads();
    int excl = sh[t] - v + s_off;
    if (gid < N_NODES) { g_rowptr[gid] = excl; g_deg[gid] = excl; }
    if (gid == 0) g_rowptr[N_NODES] = N_EDGES;
}

__global__ void k_scatter(const void* ei) {
    int e = blockIdx.x * blockDim.x + threadIdx.x;
    if (e < N_EDGES) {
        int src = ld_idx(ei, e);
        int dst = ld_idx(ei, (long)N_EDGES + e);
        int pos = atomicAdd(&g_deg[dst], 1);
        g_csr[pos] = src;
    }
}

// ---------------- aggregation: 4-way unrolled gather ----------------------
// zeroes the NEXT layer's stats buffer (parity `zpar`)
__global__ void k_agg32(const float* __restrict__ x, int zpar) {
    int t = blockIdx.x * blockDim.x + threadIdx.x;
    if (t < 128) g_fsum[zpar][t] = 0.f;
    else if (t < 256) g_fsq[zpar][t - 128] = 0.f;
    int node = t >> 5, lane = t & 31;
    if (node >= N_NODES) return;
    float acc = x[node * 32 + lane];
    int e0 = g_rowptr[node], e1 = g_rowptr[node + 1];
    int e = e0;
    for (; e + 4 <= e1; e += 4) {
        int s0 = g_csr[e], s1 = g_csr[e + 1], s2 = g_csr[e + 2], s3 = g_csr[e + 3];
        float v0 = x[s0 * 32 + lane];
        float v1 = x[s1 * 32 + lane];
        float v2 = x[s2 * 32 + lane];
        float v3 = x[s3 * 32 + lane];
        acc += v0; acc += v1; acc += v2; acc += v3;
    }
    for (; e < e1; e++) {
        int s = g_csr[e];
        acc += x[s * 32 + lane];
    }
    g_hsum[node * 32 + lane] = __float2half_rn(acc);
}

__global__ void k_agg128(int zpar) {
    int t = blockIdx.x * blockDim.x + threadIdx.x;
    if (t < 128) g_fsum[zpar][t] = 0.f;
    else if (t < 256) g_fsq[zpar][t - 128] = 0.f;
    int node = t >> 5, lane = t & 31;
    if (node >= N_NODES) return;
    const uint2* hin = (const uint2*)g_h;    // 4 halves per lane
    uint2 hv = hin[node * 32 + lane];
    float2 p0 = __half22float2(*(__half2*)&hv.x);
    float2 p1 = __half22float2(*(__half2*)&hv.y);
    float4 acc = make_float4(p0.x, p0.y, p1.x, p1.y);
    int e0 = g_rowptr[node], e1 = g_rowptr[node + 1];
    int e = e0;
    for (; e + 4 <= e1; e += 4) {
        int s0 = g_csr[e], s1 = g_csr[e + 1], s2 = g_csr[e + 2], s3 = g_csr[e + 3];
        uint2 w0 = hin[s0 * 32 + lane];
        uint2 w1 = hin[s1 * 32 + lane];
        uint2 w2 = hin[s2 * 32 + lane];
        uint2 w3 = hin[s3 * 32 + lane];
        { float2 a = __half22float2(*(__half2*)&w0.x); float2 b = __half22float2(*(__half2*)&w0.y);
          acc.x += a.x; acc.y += a.y; acc.z += b.x; acc.w += b.y; }
        { float2 a = __half22float2(*(__half2*)&w1.x); float2 b = __half22float2(*(__half2*)&w1.y);
          acc.x += a.x; acc.y += a.y; acc.z += b.x; acc.w += b.y; }
        { float2 a = __half22float2(*(__half2*)&w2.x); float2 b = __half22float2(*(__half2*)&w2.y);
          acc.x += a.x; acc.y += a.y; acc.z += b.x; acc.w += b.y; }
        { float2 a = __half22float2(*(__half2*)&w3.x); float2 b = __half22float2(*(__half2*)&w3.y);
          acc.x += a.x; acc.y += a.y; acc.z += b.x; acc.w += b.y; }
    }
    for (; e < e1; e++) {
        int s = g_csr[e];
        uint2 v = hin[s * 32 + lane];
        float2 q0 = __half22float2(*(__half2*)&v.x);
        float2 q1 = __half22float2(*(__half2*)&v.y);
        acc.x += q0.x; acc.y += q0.y; acc.z += q1.x; acc.w += q1.y;
    }
    __half2 o0 = __floats2half2_rn(acc.x, acc.y);
    __half2 o1 = __floats2half2_rn(acc.z, acc.w);
    uint2 o;
    o.x = *(uint32_t*)&o0;
    o.y = *(uint32_t*)&o1;
    ((uint2*)g_hsum)[node * 32 + lane] = o;
}

// ---------------- FP16 GEMM: packed-B frags, 3-stage cp.async ------------
#define LDAH   40                         // halves per A smem row
#define A_BYTES (128 * LDAH * 2)          // 10240
#define B_BYTES 8192                      // packed slab bytes per k-tile
#define STG_B  (A_BYTES + B_BYTES)        // 18432
#define GEMM_SMEM (3 * STG_B)             // 55296

template<bool RELU, bool OUTHALF, bool STATS>
__global__ void __launch_bounds__(256, 2)
k_mma(const __half* __restrict__ A, const __half* __restrict__ PW,
      const float* __restrict__ bias, void* __restrict__ Cv,
      int M, int N, int K, int par) {
    extern __shared__ char dsmc[];
    const int tid  = threadIdx.x;
    const int bm   = blockIdx.x * 128;
    const int nb   = blockIdx.y;
    const int bn   = nb * 128;
    const int warp = tid >> 5, lane = tid & 31;
    const int wm   = (warp & 3) * 32;
    const int wn2  = warp >> 2;
    const int wn   = wn2 * 64;
    const int gr   = lane >> 2, tg = lane & 3;
    const int T    = K >> 5;

    const uint32_t uSM = (uint32_t)__cvta_generic_to_shared(dsmc);

    float c[2][8][4];
#pragma unroll
    for (int mi = 0; mi < 2; mi++)
#pragma unroll
        for (int ni = 0; ni < 8; ni++)
#pragma unroll
            for (int j = 0; j < 4; j++) c[mi][ni][j] = 0.f;

    auto load = [&](int kt, int s) {
        int k0 = kt << 5;
        uint32_t base = uSM + (unsigned)(s * STG_B);
#pragma unroll
        for (int it = 0; it < 2; it++) {
            int idx = it * 256 + tid;
            int row = idx >> 2, cq = idx & 3;
            long ar = bm + row;
            unsigned sz = (ar < M) ? 16u : 0u;
            long arc = (ar < M) ? ar : (long)(M - 1);
            cp16(base + (unsigned)(row * (LDAH * 2) + cq * 16),
                 A + arc * K + k0 + cq * 8, sz);
        }
        const __half* slab = PW + ((long)(nb * T + kt)) * 4096;
#pragma unroll
        for (int it = 0; it < 2; it++) {
            int idx = it * 256 + tid;
            cp16(base + (unsigned)(A_BYTES + idx * 16), slab + idx * 8, 16u);
        }
        cpcommit();
    };

    load(0, 0);
    if (T > 1) load(1, 1);

    for (int i = 0; i < T; i++) {
        if (i + 1 < T) cpwait<1>(); else cpwait<0>();
        __syncthreads();

        const __half* as = (const __half*)(dsmc + (i % 3) * STG_B);
        const uint4*  bs = (const uint4*)(dsmc + (i % 3) * STG_B + A_BYTES);
#pragma unroll
        for (int kk16 = 0; kk16 < 2; kk16++) {
            uint32_t a[2][4];
#pragma unroll
            for (int mi = 0; mi < 2; mi++) {
                int r0 = wm + mi * 16 + gr;
                int kb = kk16 * 16 + 2 * tg;
                a[mi][0] = *(const uint32_t*)&as[r0 * LDAH + kb];
                a[mi][1] = *(const uint32_t*)&as[(r0 + 8) * LDAH + kb];
                a[mi][2] = *(const uint32_t*)&as[r0 * LDAH + kb + 8];
                a[mi][3] = *(const uint32_t*)&as[(r0 + 8) * LDAH + kb + 8];
            }
            uint32_t b[8][2];
            const int fb = ((kk16 * 2 + wn2) * 4) * 32 + lane;
#pragma unroll
            for (int q = 0; q < 4; q++) {
                uint4 f = bs[fb + q * 32];
                b[2 * q][0]     = f.x;
                b[2 * q][1]     = f.y;
                b[2 * q + 1][0] = f.z;
                b[2 * q + 1][1] = f.w;
            }
#pragma unroll
            for (int mi = 0; mi < 2; mi++)
#pragma unroll
                for (int ni = 0; ni < 8; ni++)
                    mma_f16(c[mi][ni], a[mi][0], a[mi][1], a[mi][2], a[mi][3],
                            b[ni][0], b[ni][1]);
        }
        if (i + 2 < T) load(i + 2, (i + 2) % 3);
    }

    // epilogue
    float ssum[8][2], ssq[8][2];
    if (STATS) {
#pragma unroll
        for (int ni = 0; ni < 8; ni++) {
            ssum[ni][0] = ssum[ni][1] = 0.f;
            ssq[ni][0] = ssq[ni][1] = 0.f;
        }
    }
#pragma unroll
    for (int mi = 0; mi < 2; mi++) {
        int r0 = bm + wm + mi * 16 + gr;
        int r1 = r0 + 8;
#pragma unroll
        for (int ni = 0; ni < 8; ni++) {
            int col = bn + wn + ni * 8 + tg * 2;
            float b0 = bias[col], b1 = bias[col + 1];
            float v0 = c[mi][ni][0] + b0, v1 = c[mi][ni][1] + b1;
            float v2 = c[mi][ni][2] + b0, v3 = c[mi][ni][3] + b1;
            if (RELU) {
                v0 = fmaxf(v0, 0.f); v1 = fmaxf(v1, 0.f);
                v2 = fmaxf(v2, 0.f); v3 = fmaxf(v3, 0.f);
            }
            if (STATS) {   // fp32 stats BEFORE fp16 store rounding
                if (r0 < M) { ssum[ni][0] += v0; ssq[ni][0] += v0 * v0;
                              ssum[ni][1] += v1; ssq[ni][1] += v1 * v1; }
                if (r1 < M) { ssum[ni][0] += v2; ssq[ni][0] += v2 * v2;
                              ssum[ni][1] += v3; ssq[ni][1] += v3 * v3; }
            }
            if (OUTHALF) {
                __half* C = (__half*)Cv;
                if (r0 < M) {
                    __half2 p = __floats2half2_rn(v0, v1);
                    *(__half2*)&C[(long)r0 * N + col] = p;
                }
                if (r1 < M) {
                    __half2 p = __floats2half2_rn(v2, v3);
                    *(__half2*)&C[(long)r1 * N + col] = p;
                }
            } else {
                float* C = (float*)Cv;
                if (r0 < M) { float2 p = make_float2(v0, v1); *(float2*)&C[(long)r0 * N + col] = p; }
                if (r1 < M) { float2 p = make_float2(v2, v3); *(float2*)&C[(long)r1 * N + col] = p; }
            }
        }
    }
    if (STATS) {
#pragma unroll
        for (int ni = 0; ni < 8; ni++)
#pragma unroll
            for (int q = 0; q < 2; q++) {
#pragma unroll
                for (int m = 4; m <= 16; m <<= 1) {
                    ssum[ni][q] += __shfl_xor_sync(0xffffffffu, ssum[ni][q], m);
                    ssq[ni][q]  += __shfl_xor_sync(0xffffffffu, ssq[ni][q], m);
                }
            }
        if (gr == 0) {
#pragma unroll
            for (int ni = 0; ni < 8; ni++) {
                int col = bn + wn + ni * 8 + tg * 2;
                atomicAdd(&g_fsum[par][col],     ssum[ni][0]);
                atomicAdd(&g_fsum[par][col + 1], ssum[ni][1]);
                atomicAdd(&g_fsq[par][col],      ssq[ni][0]);
                atomicAdd(&g_fsq[par][col + 1],  ssq[ni][1]);
            }
        }
    }
}

// ---------------- BN apply (folded coefficient computation) --------------
__global__ void __launch_bounds__(256)
k_bn_apply(const float* __restrict__ gamma, const float* __restrict__ beta, int par) {
    __shared__ float s_sc[GHC], s_sh[GHC];
    if (threadIdx.x < GHC) {
        float sc, sh;
        bn_coef(par, threadIdx.x, gamma, beta, sc, sh);
        s_sc[threadIdx.x] = sc;
        s_sh[threadIdx.x] = sh;
    }
    __syncthreads();
    int idx = blockIdx.x * blockDim.x + threadIdx.x;   // uint2 (4-half) index
    if (idx >= N_NODES * 32) return;
    int lane = idx & 31;
    uint2 hv = ((const uint2*)g_pre)[idx];
    float2 p0 = __half22float2(*(__half2*)&hv.x);
    float2 p1 = __half22float2(*(__half2*)&hv.y);
    float x0 = fmaxf(fmaf(p0.x, s_sc[lane * 4 + 0], s_sh[lane * 4 + 0]), 0.f);
    float x1 = fmaxf(fmaf(p0.y, s_sc[lane * 4 + 1], s_sh[lane * 4 + 1]), 0.f);
    float x2 = fmaxf(fmaf(p1.x, s_sc[lane * 4 + 2], s_sh[lane * 4 + 2]), 0.f);
    float x3 = fmaxf(fmaf(p1.y, s_sc[lane * 4 + 3], s_sh[lane * 4 + 3]), 0.f);
    __half2 o0 = __floats2half2_rn(x0, x1);
    __half2 o1 = __floats2half2_rn(x2, x3);
    uint2 o;
    o.x = *(uint32_t*)&o0;
    o.y = *(uint32_t*)&o1;
    ((uint2*)g_h)[idx] = o;
}

// ---------------- pool (side stream; folded coefficients) ----------------
__global__ void __launch_bounds__(GHC)
k_pool(const float* __restrict__ gamma, const float* __restrict__ beta,
       int par, int lofs) {
    int g = blockIdx.x;
    int c = threadIdx.x;
    float sc, sh;
    bn_coef(par, c, gamma, beta, sc, sh);
    int r0 = g_gstart[g], r1 = g_gstart[g + 1];
    float a0 = 0.f, a1 = 0.f;
    int r = r0;
    for (; r + 1 < r1; r += 2) {
        float v0 = __half2float(g_pre[(long)r * GHC + c]);
        float v1 = __half2float(g_pre[(long)(r + 1) * GHC + c]);
        a0 += fmaxf(fmaf(v0, sc, sh), 0.f);
        a1 += fmaxf(fmaf(v1, sc, sh), 0.f);
    }
    if (r < r1) {
        float v0 = __half2float(g_pre[(long)r * GHC + c]);
        a0 += fmaxf(fmaf(v0, sc, sh), 0.f);
    }
    int cnt = r1 - r0;
    float inv = (cnt > 0) ? (1.f / (float)cnt) : 0.f;
    g_z[(long)g * ZDIM + lofs + c] = __float2half_rn((a0 + a1) * inv);
}

// ---------------- launch ----------------
extern "C" void kernel_launch(void* const* d_in, const int* in_sizes, int n_in,
                              void* d_out, int out_size) {
    const float* x      = (const float*)d_in[0];
    const void*  ei     = d_in[1];
    const void*  batch  = d_in[2];
    const float* b1_0   = (const float*)d_in[4];
    const float* b2_0   = (const float*)d_in[6];
    const float* b1s    = (const float*)d_in[8];
    const float* b2s    = (const float*)d_in[10];
    const float* gamma  = (const float*)d_in[11];
    const float* beta   = (const float*)d_in[12];
    const float* bm1    = (const float*)d_in[14];
    const float* bm2    = (const float*)d_in[16];
    float* out = (float*)d_out;

    void *p_hsum, *p_hid, *p_pre, *p_z, *p_zh, *p_wtf;
    cudaGetSymbolAddress(&p_hsum, g_hsum);
    cudaGetSymbolAddress(&p_hid,  g_hid);
    cudaGetSymbolAddress(&p_pre,  g_pre);
    cudaGetSymbolAddress(&p_z,    g_z);
    cudaGetSymbolAddress(&p_zh,   g_zh);
    cudaGetSymbolAddress(&p_wtf,  g_wtf);
    const __half* wtf = (const __half*)p_wtf;

    static cudaStream_t s_side = nullptr;
    static cudaEvent_t  s_evb = nullptr, s_evw = nullptr;
    static cudaEvent_t  s_evf[N_LAYERS], s_evp[N_LAYERS];
    static bool init_done = false;
    if (!init_done) {
        cudaFuncSetAttribute(k_mma<true,  true,  false>, cudaFuncAttributeMaxDynamicSharedMemorySize, GEMM_SMEM);
        cudaFuncSetAttribute(k_mma<false, true,  true >, cudaFuncAttributeMaxDynamicSharedMemorySize, GEMM_SMEM);
        cudaFuncSetAttribute(k_mma<false, false, false>, cudaFuncAttributeMaxDynamicSharedMemorySize, GEMM_SMEM);
        cudaStreamCreateWithFlags(&s_side, cudaStreamNonBlocking);
        cudaEventCreateWithFlags(&s_evb, cudaEventDisableTiming);
        cudaEventCreateWithFlags(&s_evw, cudaEventDisableTiming);
        for (int l = 0; l < N_LAYERS; l++) {
            cudaEventCreateWithFlags(&s_evf[l], cudaEventDisableTiming);
            cudaEventCreateWithFlags(&s_evp[l], cudaEventDisableTiming);
        }
        init_done = true;
    }

    // ---- setup; weight packing forked to side stream ----
    k_probe<<<1, 32>>>((const unsigned int*)ei);
    cudaEventRecord(s_evb, 0);
    cudaStreamWaitEvent(s_side, s_evb, 0);
    k_init_wpack<<<(W_TOTAL / 8 + 255) / 256, 256, 0, s_side>>>(
        (const float*)d_in[3], (const float*)d_in[5],
        (const float*)d_in[7], (const float*)d_in[9],
        (const float*)d_in[13], (const float*)d_in[15]);
    cudaEventRecord(s_evw, s_side);

    k_init_graph<<<(N_NODES + 255) / 256, 256>>>(batch);
    k_deg<<<(N_EDGES + 255) / 256, 256>>>(ei);
    k_scan<<<(N_NODES + 1023) / 1024, 1024>>>();
    k_scatter<<<(N_EDGES + 255) / 256, 256>>>(ei);

    dim3 gA((N_NODES * 32 + 255) / 256);
    const int MB = (N_NODES + 127) / 128;

    cudaStreamWaitEvent(0, s_evw, 0);   // packed weights ready before first GEMM

    for (int l = 0; l < N_LAYERS; l++) {
        int K1;
        const __half *W1, *W2;
        const float *B1, *B2;
        const int par = l & 1;
        if (l == 0) {
            K1 = F_IN;
            W1 = wtf + OFF_W1_0; B1 = b1_0;
            W2 = wtf + OFF_W2_0; B2 = b2_0;
            k_agg32<<<gA, 256>>>(x, par);
        } else {
            K1 = GHC;
            W1 = wtf + OFF_W1S + (long)(l - 1) * GHC * 2 * GHC;
            B1 = b1s + (long)(l - 1) * 2 * GHC;
            W2 = wtf + OFF_W2S + (long)(l - 1) * 2 * GHC * GHC;
            B2 = b2s + (long)(l - 1) * GHC;
            k_agg128<<<gA, 256>>>(par);
        }
        dim3 g1(MB, (2 * GHC) / 128);
        k_mma<true, true, false><<<g1, 256, GEMM_SMEM>>>(
            (const __half*)p_hsum, W1, B1, p_hid, N_NODES, 2 * GHC, K1, 0);
        if (l > 0) cudaStreamWaitEvent(0, s_evp[l - 1], 0);   // pool(l-1) done reading g_pre
        dim3 g2(MB, GHC / 128);
        k_mma<false, true, true><<<g2, 256, GEMM_SMEM>>>(
            (const __half*)p_hid, W2, B2, p_pre, N_NODES, GHC, 2 * GHC, par);
        // fork: pool(l) on side stream (computes BN coefficients itself)
        cudaEventRecord(s_evf[l], 0);
        cudaStreamWaitEvent(s_side, s_evf[l], 0);
        k_pool<<<N_GRAPHS, GHC, 0, s_side>>>(gamma + l * GHC, beta + l * GHC, par, l * GHC);
        cudaEventRecord(s_evp[l], s_side);
        // apply (main): g_h needed by next layer's aggregation
        if (l + 1 < N_LAYERS)
            k_bn_apply<<<(N_NODES * 32 + 255) / 256, 256>>>(gamma + l * GHC, beta + l * GHC, par);
    }

    // join last pool, then final MLP
    cudaStreamWaitEvent(0, s_evp[N_LAYERS - 1], 0);
    {
        dim3 g1((N_GRAPHS + 127) / 128, NHID / 128);
        k_mma<true, true, false><<<g1, 256, GEMM_SMEM>>>(
            (const __half*)p_z, wtf + OFF_WM1, bm1, p_zh, N_GRAPHS, NHID, ZDIM, 0);
        dim3 g2((N_GRAPHS + 127) / 128, NOUT / 128);
        k_mma<false, false, false><<<g2, 256, GEMM_SMEM>>>(
            (const __half*)p_zh, wtf + OFF_WM2, bm2, out, N_GRAPHS, NOUT, NHID, 0);
    }
}

// round 16
// speedup vs baseline: 1.3780x; 1.3780x over previous
#include <cuda_runtime.h>
#include <cuda_fp16.h>
#include <math.h>
#include <stdint.h>

#define N_NODES 100000
#define N_EDGES 600000
#define N_GRAPHS 1024
#define F_IN 32
#define GHC 128
#define NHID 512
#define NOUT 256
#define N_LAYERS 5
#define BN_EPS 1e-5f
#define ZDIM (N_LAYERS * GHC)   // 640

// packed fp16 weight offsets (elements)
#define OFF_W1_0 0
#define OFF_W2_0 8192
#define OFF_W1S  40960
#define OFF_W2S  172032
#define OFF_WM1  303104
#define OFF_WM2  630784
#define W_TOTAL  761856

// ---------------- device scratch ----------------
__device__ __half g_hsum[N_NODES * GHC];
__device__ __half g_hid [N_NODES * 2 * GHC];
__device__ __half g_pre [N_NODES * GHC];
__device__ __half g_h   [N_NODES * GHC];
__device__ __half g_wtf [W_TOTAL];           // PACKED fp16 weights (frag order)
__device__ int    g_rowptr[N_NODES + 1];
__device__ int    g_deg   [N_NODES];
__device__ int    g_csr   [N_EDGES];
__device__ int    g_blocktotals[128];
__device__ volatile int g_scanflag[128];
__device__ float  g_fsum[GHC], g_fsq[GHC];
__device__ float  g_scale[GHC], g_shift[GHC];
__device__ __half g_z  [N_GRAPHS * ZDIM];
__device__ __half g_zh [N_GRAPHS * NHID];
__device__ int    g_gstart[N_GRAPHS + 1];
__device__ int    g_is64;

// ---------------- helpers ----------------
__device__ __forceinline__ int ld_idx(const void* p, long i) {
    if (g_is64) return (int)((const long long*)p)[i];
    return ((const int*)p)[i];
}
__device__ __forceinline__ void cp16(uint32_t saddr, const void* g, unsigned sz) {
    asm volatile("cp.async.cg.shared.global [%0], [%1], 16, %2;"
                 :: "r"(saddr), "l"(g), "r"(sz));
}
__device__ __forceinline__ void cpcommit() { asm volatile("cp.async.commit_group;"); }
template<int W> __device__ __forceinline__ void cpwait() {
    asm volatile("cp.async.wait_group %0;" :: "n"(W));
}
__device__ __forceinline__ void mma_f16(float* c, uint32_t a0, uint32_t a1,
                                        uint32_t a2, uint32_t a3,
                                        uint32_t b0, uint32_t b1) {
    asm volatile(
        "mma.sync.aligned.m16n8k16.row.col.f32.f16.f16.f32 "
        "{%0,%1,%2,%3},{%4,%5,%6,%7},{%8,%9},{%0,%1,%2,%3};"
        : "+f"(c[0]), "+f"(c[1]), "+f"(c[2]), "+f"(c[3])
        : "r"(a0), "r"(a1), "r"(a2), "r"(a3), "r"(b0), "r"(b1));
}

__global__ void k_probe(const unsigned int* ei_words) {
    if (threadIdx.x == 0 && blockIdx.x == 0) {
        unsigned int nz = 0;
        for (int i = 0; i < 256; i++) nz |= ei_words[2 * i + 1];
        g_is64 = (nz == 0) ? 1 : 0;
    }
}

__global__ void k_init_graph(const void* batch) {
    int i = blockIdx.x * blockDim.x + threadIdx.x;
    if (i < N_NODES) g_deg[i] = 0;
    if (i < 128) { g_scanflag[i] = 0; g_blocktotals[i] = 0; }
    if (i <= N_GRAPHS) {
        int g = i, lo = 0, hi = N_NODES;
        while (lo < hi) {
            int mid = (lo + hi) >> 1;
            if (ld_idx(batch, mid) < g) lo = mid + 1; else hi = mid;
        }
        g_gstart[i] = lo;
    }
}

// pack one uint4 slot (8 halves) of a weight matrix into m16n8k16 B-frag order
__device__ __forceinline__ void pack_slot(const float* W, int K, int N,
                                          long rel4, __half* dst) {
    int lane = (int)(rel4 & 31);
    int q    = (int)((rel4 >> 5) & 3);
    int wn2  = (int)((rel4 >> 7) & 1);
    int kk16 = (int)((rel4 >> 8) & 1);
    long slab = rel4 >> 9;
    int ktiles = K >> 5;
    int nb = (int)(slab / ktiles);
    int kt = (int)(slab % ktiles);
    int gr = lane >> 2, tg = lane & 3;
    int kb = kt * 32 + kk16 * 16 + 2 * tg;
    int c0 = nb * 128 + wn2 * 64 + q * 16 + gr;
    int c1 = c0 + 8;
    __half h[8];
    h[0] = __float2half_rn(W[(long)kb * N + c0]);
    h[1] = __float2half_rn(W[(long)(kb + 1) * N + c0]);
    h[2] = __float2half_rn(W[(long)(kb + 8) * N + c0]);
    h[3] = __float2half_rn(W[(long)(kb + 9) * N + c0]);
    h[4] = __float2half_rn(W[(long)kb * N + c1]);
    h[5] = __float2half_rn(W[(long)(kb + 1) * N + c1]);
    h[6] = __float2half_rn(W[(long)(kb + 8) * N + c1]);
    h[7] = __float2half_rn(W[(long)(kb + 9) * N + c1]);
    *(uint4*)dst = *(uint4*)h;
}

__global__ void k_init_wpack(const float* W1_0, const float* W2_0,
                             const float* W1s, const float* W2s,
                             const float* Wm1, const float* Wm2) {
    int i = blockIdx.x * blockDim.x + threadIdx.x;   // uint4 slot
    if (i >= W_TOTAL / 8) return;
    long f = (long)i * 8;
    __half* dst = &g_wtf[f];
    if (f < OFF_W2_0) {
        pack_slot(W1_0, 32, 256, f / 8, dst);
    } else if (f < OFF_W1S) {
        pack_slot(W2_0, 256, 128, (f - OFF_W2_0) / 8, dst);
    } else if (f < OFF_W2S) {
        long rel = f - OFF_W1S;
        int l = (int)(rel / 32768);
        pack_slot(W1s + (long)l * 32768, 128, 256, (rel % 32768) / 8, dst);
    } else if (f < OFF_WM1) {
        long rel = f - OFF_W2S;
        int l = (int)(rel / 32768);
        pack_slot(W2s + (long)l * 32768, 256, 128, (rel % 32768) / 8, dst);
    } else if (f < OFF_WM2) {
        pack_slot(Wm1, 640, 512, (f - OFF_WM1) / 8, dst);
    } else {
        pack_slot(Wm2, 512, 256, (f - OFF_WM2) / 8, dst);
    }
}

__global__ void k_deg(const void* ei) {
    int e = blockIdx.x * blockDim.x + threadIdx.x;
    if (e < N_EDGES) {
        int dst = ld_idx(ei, (long)N_EDGES + e);
        atomicAdd(&g_deg[dst], 1);
    }
}

__global__ void k_scan() {
    __shared__ int sh[1024];
    __shared__ int s_off;
    int b = blockIdx.x, t = threadIdx.x;
    int gid = b * 1024 + t;
    int v = (gid < N_NODES) ? g_deg[gid] : 0;
    sh[t] = v;
    __syncthreads();
    for (int off = 1; off < 1024; off <<= 1) {
        int tmp = (t >= off) ? sh[t - off] : 0;
        __syncthreads();
        sh[t] += tmp;
        __syncthreads();
    }
    if (t == 1023) {
        g_blocktotals[b] = sh[1023];
        __threadfence();
        g_scanflag[b] = 1;
    }
    if (t == 0) s_off = 0;
    __syncthreads();
    if (t < b) {
        while (g_scanflag[t] == 0) {}
        int tot = atomicAdd(&g_blocktotals[t], 0);
        atomicAdd(&s_off, tot);
    }
    __syncthreads();
    int excl = sh[t] - v + s_off;
    if (gid < N_NODES) { g_rowptr[gid] = excl; g_deg[gid] = excl; }
    if (gid == 0) g_rowptr[N_NODES] = N_EDGES;
}

__global__ void k_scatter(const void* ei) {
    int e = blockIdx.x * blockDim.x + threadIdx.x;
    if (e < N_EDGES) {
        int src = ld_idx(ei, e);
        int dst = ld_idx(ei, (long)N_EDGES + e);
        int pos = atomicAdd(&g_deg[dst], 1);
        g_csr[pos] = src;
    }
}

// ---------------- aggregation: 4-way unrolled gather ----------------------
__global__ void k_agg32(const float* __restrict__ x) {
    int t = blockIdx.x * blockDim.x + threadIdx.x;
    if (t < 128) g_fsum[t] = 0.f;
    else if (t < 256) g_fsq[t - 128] = 0.f;
    int node = t >> 5, lane = t & 31;
    if (node >= N_NODES) return;
    float acc = x[node * 32 + lane];
    int e0 = g_rowptr[node], e1 = g_rowptr[node + 1];
    int e = e0;
    for (; e + 4 <= e1; e += 4) {
        int s0 = g_csr[e], s1 = g_csr[e + 1], s2 = g_csr[e + 2], s3 = g_csr[e + 3];
        float v0 = x[s0 * 32 + lane];
        float v1 = x[s1 * 32 + lane];
        float v2 = x[s2 * 32 + lane];
        float v3 = x[s3 * 32 + lane];
        acc += v0; acc += v1; acc += v2; acc += v3;
    }
    for (; e < e1; e++) {
        int s = g_csr[e];
        acc += x[s * 32 + lane];
    }
    g_hsum[node * 32 + lane] = __float2half_rn(acc);
}

__global__ void k_agg128() {
    int t = blockIdx.x * blockDim.x + threadIdx.x;
    if (t < 128) g_fsum[t] = 0.f;
    else if (t < 256) g_fsq[t - 128] = 0.f;
    int node = t >> 5, lane = t & 31;
    if (node >= N_NODES) return;
    const uint2* hin = (const uint2*)g_h;    // 4 halves per lane
    uint2 hv = hin[node * 32 + lane];
    float2 p0 = __half22float2(*(__half2*)&hv.x);
    float2 p1 = __half22float2(*(__half2*)&hv.y);
    float4 acc = make_float4(p0.x, p0.y, p1.x, p1.y);
    int e0 = g_rowptr[node], e1 = g_rowptr[node + 1];
    int e = e0;
    for (; e + 4 <= e1; e += 4) {
        int s0 = g_csr[e], s1 = g_csr[e + 1], s2 = g_csr[e + 2], s3 = g_csr[e + 3];
        uint2 w0 = hin[s0 * 32 + lane];
        uint2 w1 = hin[s1 * 32 + lane];
        uint2 w2 = hin[s2 * 32 + lane];
        uint2 w3 = hin[s3 * 32 + lane];
        { float2 a = __half22float2(*(__half2*)&w0.x); float2 b = __half22float2(*(__half2*)&w0.y);
          acc.x += a.x; acc.y += a.y; acc.z += b.x; acc.w += b.y; }
        { float2 a = __half22float2(*(__half2*)&w1.x); float2 b = __half22float2(*(__half2*)&w1.y);
          acc.x += a.x; acc.y += a.y; acc.z += b.x; acc.w += b.y; }
        { float2 a = __half22float2(*(__half2*)&w2.x); float2 b = __half22float2(*(__half2*)&w2.y);
          acc.x += a.x; acc.y += a.y; acc.z += b.x; acc.w += b.y; }
        { float2 a = __half22float2(*(__half2*)&w3.x); float2 b = __half22float2(*(__half2*)&w3.y);
          acc.x += a.x; acc.y += a.y; acc.z += b.x; acc.w += b.y; }
    }
    for (; e < e1; e++) {
        int s = g_csr[e];
        uint2 v = hin[s * 32 + lane];
        float2 q0 = __half22float2(*(__half2*)&v.x);
        float2 q1 = __half22float2(*(__half2*)&v.y);
        acc.x += q0.x; acc.y += q0.y; acc.z += q1.x; acc.w += q1.y;
    }
    __half2 o0 = __floats2half2_rn(acc.x, acc.y);
    __half2 o1 = __floats2half2_rn(acc.z, acc.w);
    uint2 o;
    o.x = *(uint32_t*)&o0;
    o.y = *(uint32_t*)&o1;
    ((uint2*)g_hsum)[node * 32 + lane] = o;
}

// ---------------- FP16 GEMM: packed-B frags, 3-stage cp.async ------------
#define LDAH   40                         // halves per A smem row
#define A_BYTES (128 * LDAH * 2)          // 10240
#define B_BYTES 8192                      // packed slab bytes per k-tile
#define STG_B  (A_BYTES + B_BYTES)        // 18432
#define GEMM_SMEM (3 * STG_B)             // 55296

template<bool RELU, bool OUTHALF, bool STATS>
__global__ void __launch_bounds__(256, 2)
k_mma(const __half* __restrict__ A, const __half* __restrict__ PW,
      const float* __restrict__ bias, void* __restrict__ Cv,
      int M, int N, int K) {
    extern __shared__ char dsmc[];
    const int tid  = threadIdx.x;
    const int bm   = blockIdx.x * 128;
    const int nb   = blockIdx.y;
    const int bn   = nb * 128;
    const int warp = tid >> 5, lane = tid & 31;
    const int wm   = (warp & 3) * 32;
    const int wn2  = warp >> 2;
    const int wn   = wn2 * 64;
    const int gr   = lane >> 2, tg = lane & 3;
    const int T    = K >> 5;

    const uint32_t uSM = (uint32_t)__cvta_generic_to_shared(dsmc);

    float c[2][8][4];
#pragma unroll
    for (int mi = 0; mi < 2; mi++)
#pragma unroll
        for (int ni = 0; ni < 8; ni++)
#pragma unroll
            for (int j = 0; j < 4; j++) c[mi][ni][j] = 0.f;

    auto load = [&](int kt, int s) {
        int k0 = kt << 5;
        uint32_t base = uSM + (unsigned)(s * STG_B);
#pragma unroll
        for (int it = 0; it < 2; it++) {
            int idx = it * 256 + tid;
            int row = idx >> 2, cq = idx & 3;
            long ar = bm + row;
            unsigned sz = (ar < M) ? 16u : 0u;
            long arc = (ar < M) ? ar : (long)(M - 1);
            cp16(base + (unsigned)(row * (LDAH * 2) + cq * 16),
                 A + arc * K + k0 + cq * 8, sz);
        }
        const __half* slab = PW + ((long)(nb * T + kt)) * 4096;
#pragma unroll
        for (int it = 0; it < 2; it++) {
            int idx = it * 256 + tid;
            cp16(base + (unsigned)(A_BYTES + idx * 16), slab + idx * 8, 16u);
        }
        cpcommit();
    };

    load(0, 0);
    if (T > 1) load(1, 1);

    for (int i = 0; i < T; i++) {
        if (i + 1 < T) cpwait<1>(); else cpwait<0>();
        __syncthreads();

        const __half* as = (const __half*)(dsmc + (i % 3) * STG_B);
        const uint4*  bs = (const uint4*)(dsmc + (i % 3) * STG_B + A_BYTES);
#pragma unroll
        for (int kk16 = 0; kk16 < 2; kk16++) {
            uint32_t a[2][4];
#pragma unroll
            for (int mi = 0; mi < 2; mi++) {
                int r0 = wm + mi * 16 + gr;
                int kb = kk16 * 16 + 2 * tg;
                a[mi][0] = *(const uint32_t*)&as[r0 * LDAH + kb];
                a[mi][1] = *(const uint32_t*)&as[(r0 + 8) * LDAH + kb];
                a[mi][2] = *(const uint32_t*)&as[r0 * LDAH + kb + 8];
                a[mi][3] = *(const uint32_t*)&as[(r0 + 8) * LDAH + kb + 8];
            }
            uint32_t b[8][2];
            const int fb = ((kk16 * 2 + wn2) * 4) * 32 + lane;
#pragma unroll
            for (int q = 0; q < 4; q++) {
                uint4 f = bs[fb + q * 32];
                b[2 * q][0]     = f.x;
                b[2 * q][1]     = f.y;
                b[2 * q + 1][0] = f.z;
                b[2 * q + 1][1] = f.w;
            }
#pragma unroll
            for (int mi = 0; mi < 2; mi++)
#pragma unroll
                for (int ni = 0; ni < 8; ni++)
                    mma_f16(c[mi][ni], a[mi][0], a[mi][1], a[mi][2], a[mi][3],
                            b[ni][0], b[ni][1]);
        }
        if (i + 2 < T) load(i + 2, (i + 2) % 3);
    }

    // epilogue
    float ssum[8][2], ssq[8][2];
    if (STATS) {
#pragma unroll
        for (int ni = 0; ni < 8; ni++) {
            ssum[ni][0] = ssum[ni][1] = 0.f;
            ssq[ni][0] = ssq[ni][1] = 0.f;
        }
    }
#pragma unroll
    for (int mi = 0; mi < 2; mi++) {
        int r0 = bm + wm + mi * 16 + gr;
        int r1 = r0 + 8;
#pragma unroll
        for (int ni = 0; ni < 8; ni++) {
            int col = bn + wn + ni * 8 + tg * 2;
            float b0 = bias[col], b1 = bias[col + 1];
            float v0 = c[mi][ni][0] + b0, v1 = c[mi][ni][1] + b1;
            float v2 = c[mi][ni][2] + b0, v3 = c[mi][ni][3] + b1;
            if (RELU) {
                v0 = fmaxf(v0, 0.f); v1 = fmaxf(v1, 0.f);
                v2 = fmaxf(v2, 0.f); v3 = fmaxf(v3, 0.f);
            }
            if (STATS) {   // fp32 stats BEFORE fp16 store rounding
                if (r0 < M) { ssum[ni][0] += v0; ssq[ni][0] += v0 * v0;
                              ssum[ni][1] += v1; ssq[ni][1] += v1 * v1; }
                if (r1 < M) { ssum[ni][0] += v2; ssq[ni][0] += v2 * v2;
                              ssum[ni][1] += v3; ssq[ni][1] += v3 * v3; }
            }
            if (OUTHALF) {
                __half* C = (__half*)Cv;
                if (r0 < M) {
                    __half2 p = __floats2half2_rn(v0, v1);
                    *(__half2*)&C[(long)r0 * N + col] = p;
                }
                if (r1 < M) {
                    __half2 p = __floats2half2_rn(v2, v3);
                    *(__half2*)&C[(long)r1 * N + col] = p;
                }
            } else {
                float* C = (float*)Cv;
                if (r0 < M) { float2 p = make_float2(v0, v1); *(float2*)&C[(long)r0 * N + col] = p; }
                if (r1 < M) { float2 p = make_float2(v2, v3); *(float2*)&C[(long)r1 * N + col] = p; }
            }
        }
    }
    if (STATS) {
#pragma unroll
        for (int ni = 0; ni < 8; ni++)
#pragma unroll
            for (int q = 0; q < 2; q++) {
#pragma unroll
                for (int m = 4; m <= 16; m <<= 1) {
                    ssum[ni][q] += __shfl_xor_sync(0xffffffffu, ssum[ni][q], m);
                    ssq[ni][q]  += __shfl_xor_sync(0xffffffffu, ssq[ni][q], m);
                }
            }
        if (gr == 0) {
#pragma unroll
            for (int ni = 0; ni < 8; ni++) {
                int col = bn + wn + ni * 8 + tg * 2;
                atomicAdd(&g_fsum[col],     ssum[ni][0]);
                atomicAdd(&g_fsum[col + 1], ssum[ni][1]);
                atomicAdd(&g_fsq[col],      ssq[ni][0]);
                atomicAdd(&g_fsq[col + 1],  ssq[ni][1]);
            }
        }
    }
}

// ---------------- BatchNorm finalize, apply, pool -------------------------
__global__ void k_bn_final(const float* __restrict__ gamma, const float* __restrict__ beta) {
    int c = threadIdx.x;
    double mu = (double)g_fsum[c] / (double)N_NODES;
    double var = (double)g_fsq[c] / (double)N_NODES - mu * mu;
    double inv = 1.0 / sqrt(var + (double)BN_EPS);
    double sc = (double)gamma[c] * inv;
    g_scale[c] = (float)sc;
    g_shift[c] = (float)((double)beta[c] - mu * sc);
}

__global__ void __launch_bounds__(256)
k_bn_apply() {
    int idx = blockIdx.x * blockDim.x + threadIdx.x;   // uint2 (4-half) index
    if (idx >= N_NODES * 32) return;
    int lane = idx & 31;
    float4 sc = ((const float4*)g_scale)[lane];
    float4 sh = ((const float4*)g_shift)[lane];
    uint2 hv = ((const uint2*)g_pre)[idx];
    float2 p0 = __half22float2(*(__half2*)&hv.x);
    float2 p1 = __half22float2(*(__half2*)&hv.y);
    float x0 = fmaxf(fmaf(p0.x, sc.x, sh.x), 0.f);
    float x1 = fmaxf(fmaf(p0.y, sc.y, sh.y), 0.f);
    float x2 = fmaxf(fmaf(p1.x, sc.z, sh.z), 0.f);
    float x3 = fmaxf(fmaf(p1.y, sc.w, sh.w), 0.f);
    __half2 o0 = __floats2half2_rn(x0, x1);
    __half2 o1 = __floats2half2_rn(x2, x3);
    uint2 o;
    o.x = *(uint32_t*)&o0;
    o.y = *(uint32_t*)&o1;
    ((uint2*)g_h)[idx] = o;
}

__global__ void __launch_bounds__(GHC)
k_pool(int lofs) {
    int g = blockIdx.x;
    int c = threadIdx.x;
    int r0 = g_gstart[g], r1 = g_gstart[g + 1];
    float sc = g_scale[c], sh = g_shift[c];
    float a0 = 0.f, a1 = 0.f;
    int r = r0;
    for (; r + 1 < r1; r += 2) {
        float v0 = __half2float(g_pre[(long)r * GHC + c]);
        float v1 = __half2float(g_pre[(long)(r + 1) * GHC + c]);
        a0 += fmaxf(fmaf(v0, sc, sh), 0.f);
        a1 += fmaxf(fmaf(v1, sc, sh), 0.f);
    }
    if (r < r1) {
        float v0 = __half2float(g_pre[(long)r * GHC + c]);
        a0 += fmaxf(fmaf(v0, sc, sh), 0.f);
    }
    int cnt = r1 - r0;
    float inv = (cnt > 0) ? (1.f / (float)cnt) : 0.f;
    g_z[(long)g * ZDIM + lofs + c] = __float2half_rn((a0 + a1) * inv);
}

// ---------------- launch ----------------
extern "C" void kernel_launch(void* const* d_in, const int* in_sizes, int n_in,
                              void* d_out, int out_size) {
    const float* x      = (const float*)d_in[0];
    const void*  ei     = d_in[1];
    const void*  batch  = d_in[2];
    const float* b1_0   = (const float*)d_in[4];
    const float* b2_0   = (const float*)d_in[6];
    const float* b1s    = (const float*)d_in[8];
    const float* b2s    = (const float*)d_in[10];
    const float* gamma  = (const float*)d_in[11];
    const float* beta   = (const float*)d_in[12];
    const float* bm1    = (const float*)d_in[14];
    const float* bm2    = (const float*)d_in[16];
    float* out = (float*)d_out;

    void *p_hsum, *p_hid, *p_pre, *p_z, *p_zh, *p_wtf;
    cudaGetSymbolAddress(&p_hsum, g_hsum);
    cudaGetSymbolAddress(&p_hid,  g_hid);
    cudaGetSymbolAddress(&p_pre,  g_pre);
    cudaGetSymbolAddress(&p_z,    g_z);
    cudaGetSymbolAddress(&p_zh,   g_zh);
    cudaGetSymbolAddress(&p_wtf,  g_wtf);
    const __half* wtf = (const __half*)p_wtf;

    static cudaStream_t s_side = nullptr;
    static cudaEvent_t  s_evb = nullptr, s_evw = nullptr;
    static cudaEvent_t  s_evf[N_LAYERS], s_evp[N_LAYERS];
    static bool init_done = false;
    if (!init_done) {
        cudaFuncSetAttribute(k_mma<true,  true,  false>, cudaFuncAttributeMaxDynamicSharedMemorySize, GEMM_SMEM);
        cudaFuncSetAttribute(k_mma<false, true,  true >, cudaFuncAttributeMaxDynamicSharedMemorySize, GEMM_SMEM);
        cudaFuncSetAttribute(k_mma<false, false, false>, cudaFuncAttributeMaxDynamicSharedMemorySize, GEMM_SMEM);
        cudaStreamCreateWithFlags(&s_side, cudaStreamNonBlocking);
        cudaEventCreateWithFlags(&s_evb, cudaEventDisableTiming);
        cudaEventCreateWithFlags(&s_evw, cudaEventDisableTiming);
        for (int l = 0; l < N_LAYERS; l++) {
            cudaEventCreateWithFlags(&s_evf[l], cudaEventDisableTiming);
            cudaEventCreateWithFlags(&s_evp[l], cudaEventDisableTiming);
        }
        init_done = true;
    }

    // ---- setup; weight packing forked to side stream ----
    k_probe<<<1, 32>>>((const unsigned int*)ei);
    cudaEventRecord(s_evb, 0);
    cudaStreamWaitEvent(s_side, s_evb, 0);
    k_init_wpack<<<(W_TOTAL / 8 + 255) / 256, 256, 0, s_side>>>(
        (const float*)d_in[3], (const float*)d_in[5],
        (const float*)d_in[7], (const float*)d_in[9],
        (const float*)d_in[13], (const float*)d_in[15]);
    cudaEventRecord(s_evw, s_side);

    k_init_graph<<<(N_NODES + 255) / 256, 256>>>(batch);
    k_deg<<<(N_EDGES + 255) / 256, 256>>>(ei);
    k_scan<<<(N_NODES + 1023) / 1024, 1024>>>();
    k_scatter<<<(N_EDGES + 255) / 256, 256>>>(ei);

    dim3 gA((N_NODES * 32 + 255) / 256);
    const int MB = (N_NODES + 127) / 128;

    cudaStreamWaitEvent(0, s_evw, 0);   // packed weights ready before first GEMM

    for (int l = 0; l < N_LAYERS; l++) {
        int K1;
        const __half *W1, *W2;
        const float *B1, *B2;
        if (l == 0) {
            K1 = F_IN;
            W1 = wtf + OFF_W1_0; B1 = b1_0;
            W2 = wtf + OFF_W2_0; B2 = b2_0;
            k_agg32<<<gA, 256>>>(x);
        } else {
            K1 = GHC;
            W1 = wtf + OFF_W1S + (long)(l - 1) * GHC * 2 * GHC;
            B1 = b1s + (long)(l - 1) * 2 * GHC;
            W2 = wtf + OFF_W2S + (long)(l - 1) * 2 * GHC * GHC;
            B2 = b2s + (long)(l - 1) * GHC;
            k_agg128<<<gA, 256>>>();
        }
        dim3 g1(MB, (2 * GHC) / 128);
        k_mma<true, true, false><<<g1, 256, GEMM_SMEM>>>(
            (const __half*)p_hsum, W1, B1, p_hid, N_NODES, 2 * GHC, K1);
        if (l > 0) cudaStreamWaitEvent(0, s_evp[l - 1], 0);   // pool(l-1) done reading g_pre
        dim3 g2(MB, GHC / 128);
        k_mma<false, true, true><<<g2, 256, GEMM_SMEM>>>(
            (const __half*)p_hid, W2, B2, p_pre, N_NODES, GHC, 2 * GHC);
        k_bn_final<<<1, GHC>>>(gamma + l * GHC, beta + l * GHC);
        // fork: pool(l) on side stream
        cudaEventRecord(s_evf[l], 0);
        cudaStreamWaitEvent(s_side, s_evf[l], 0);
        k_pool<<<N_GRAPHS, GHC, 0, s_side>>>(l * GHC);
        cudaEventRecord(s_evp[l], s_side);
        // apply (main): g_h needed only by the NEXT layer's aggregation
        if (l + 1 < N_LAYERS)
            k_bn_apply<<<(N_NODES * 32 + 255) / 256, 256>>>();
    }

    // join last pool, then final MLP
    cudaStreamWaitEvent(0, s_evp[N_LAYERS - 1], 0);
    {
        dim3 g1((N_GRAPHS + 127) / 128, NHID / 128);
        k_mma<true, true, false><<<g1, 256, GEMM_SMEM>>>(
            (const __half*)p_z, wtf + OFF_WM1, bm1, p_zh, N_GRAPHS, NHID, ZDIM);
        dim3 g2((N_GRAPHS + 127) / 128, NOUT / 128);
        k_mma<false, false, false><<<g2, 256, GEMM_SMEM>>>(
            (const __half*)p_zh, wtf + OFF_WM2, bm2, out, N_GRAPHS, NOUT, NHID);
    }
}